// round 4
// baseline (speedup 1.0000x reference)
#include <cuda_runtime.h>

#define NNAT 16
#define MAX_TILES 200000

__device__ int   g_counts[MAX_TILES * NNAT];
// [0,64): sum tile_pos; [64,128): sum count_t*pte; [128,144): nation totals; [144,146): terrain counts
__device__ float g_acc[160];
__device__ float g_u[64];          // W_tile_top @ policy_w
__device__ float g_v[64];          // W_piece_bot @ policy_w
__device__ float g_q[16];          // (nation_emb @ W_piece_top) @ policy_w
__device__ float g_terrsc[2];      // (terrain_emb @ W_tile_bot) @ policy_w
__device__ float g_nproj[16 * 64]; // nation_emb @ W_piece_top
__device__ float g_tproj[2 * 64];  // terrain_emb @ W_tile_bot
__device__ float g_c0;             // (tile_fc_b + nation_emb[active]) . w + policy_b
__device__ float g_pbdot;          // piece_fc_b . w
__device__ unsigned int g_done;    // last-block epilogue counter

// Blocks 0..591 zero scratch; block 592 folds parameters with 256 threads.
__global__ void k_zero_pre(int n_counts,
                           const float* __restrict__ tile_fc_w,
                           const float* __restrict__ tile_fc_b,
                           const float* __restrict__ piece_fc_w,
                           const float* __restrict__ piece_fc_b,
                           const float* __restrict__ tile_policy_w,
                           const float* __restrict__ tile_policy_b,
                           const float* __restrict__ nation_emb,
                           const float* __restrict__ terrain_emb,
                           const int*   __restrict__ active_nation)
{
    if (blockIdx.x < 592) {
        int i = blockIdx.x * blockDim.x + threadIdx.x;
        int stride = 592 * blockDim.x;
        for (int k = i; k < n_counts; k += stride) g_counts[k] = 0;
        if (i < 160) g_acc[i] = 0.f;
        if (i == 0) g_done = 0u;
        return;
    }

    __shared__ float w[64];
    int tid = threadIdx.x;
    if (tid < 64) w[tid] = tile_policy_w[tid];
    __syncthreads();

    #pragma unroll
    for (int r = 0; r < 4; r++) {
        int idx = tid + 256 * r;        // 0..1023
        int n = idx >> 6, j = idx & 63;
        float s = 0.f;
        for (int k = 0; k < 64; k++)
            s += nation_emb[n * 64 + k] * piece_fc_w[k * 64 + j];
        g_nproj[idx] = s;
    }

    if (tid < 64) {
        float s = 0.f;
        for (int c = 0; c < 64; c++) s += tile_fc_w[tid * 64 + c] * w[c];
        g_u[tid] = s;
    } else if (tid < 128) {
        int j = tid - 64;
        float s = 0.f;
        for (int c = 0; c < 64; c++) s += piece_fc_w[(64 + j) * 64 + c] * w[c];
        g_v[j] = s;
    } else {
        int idx = tid - 128;            // 0..127
        int e = idx >> 6, j = idx & 63;
        float s = 0.f;
        for (int k = 0; k < 64; k++)
            s += terrain_emb[e * 64 + k] * tile_fc_w[(64 + k) * 64 + j];
        g_tproj[idx] = s;
    }
    __syncthreads();

    if (tid < 16) {
        float s = 0.f;
        for (int c = 0; c < 64; c++) s += g_nproj[tid * 64 + c] * w[c];
        g_q[tid] = s;
    } else if (tid < 18) {
        int e = tid - 16;
        float s = 0.f;
        for (int c = 0; c < 64; c++) s += g_tproj[e * 64 + c] * w[c];
        g_terrsc[e] = s;
    } else if (tid == 18) {
        float s = 0.f;
        for (int c = 0; c < 64; c++) s += piece_fc_b[c] * w[c];
        g_pbdot = s;
    } else if (tid == 19) {
        int an = active_nation[0];
        float s = 0.f;
        for (int c = 0; c < 64; c++)
            s += (tile_fc_b[c] + nation_emb[an * 64 + c]) * w[c];
        g_c0 = s + tile_policy_b[0];
    }
}

__global__ void k_hist(const int* __restrict__ nation_idxs,
                       const int* __restrict__ piece_tile_idxs,
                       int P)
{
    int i = blockIdx.x * blockDim.x + threadIdx.x;
    int P4 = P >> 2;
    if (i < P4) {
        int4 n4 = reinterpret_cast<const int4*>(nation_idxs)[i];
        int4 t4 = reinterpret_cast<const int4*>(piece_tile_idxs)[i];
        atomicAdd(&g_counts[t4.x * NNAT + n4.x], 1);
        atomicAdd(&g_counts[t4.y * NNAT + n4.y], 1);
        atomicAdd(&g_counts[t4.z * NNAT + n4.z], 1);
        atomicAdd(&g_counts[t4.w * NNAT + n4.w], 1);
    }
    int tail = P4 * 4 + i;
    if (i < (P & 3)) {
        atomicAdd(&g_counts[piece_tile_idxs[tail] * NNAT + nation_idxs[tail]], 1);
    }
}

// Warp layout: 2 half-warps of 16 lanes; each half handles one tile per row,
// lane covers 4 dims via float4. 8 tiles per warp-iteration.
// Last block to finish runs the pooled/value epilogue inline.
__global__ void __launch_bounds__(256, 3)
k_tiles(const int*   __restrict__ tile_idxs,
        const int*   __restrict__ terrain,
        const float* __restrict__ tile_pos_emb,
        const float* __restrict__ piece_tile_emb,
        float*       __restrict__ out,
        int T, int P,
        const float* __restrict__ tile_fc_w,
        const float* __restrict__ tile_fc_b,
        const float* __restrict__ piece_fc_w,
        const float* __restrict__ piece_fc_b,
        const float* __restrict__ nation_emb,
        const int*   __restrict__ active_nation,
        const float* __restrict__ value_w1,
        const float* __restrict__ value_b1,
        const float* __restrict__ value_w2,
        const float* __restrict__ value_b2,
        const float* __restrict__ end_turn_logit)
{
    int lane = threadIdx.x & 31;
    int sub  = lane & 15;    // dim group: dims 4*sub..4*sub+3; also nation id
    int half = lane >> 4;    // which tile of the pair
    int gwid = (blockIdx.x * blockDim.x + threadIdx.x) >> 5;
    int nw   = (gridDim.x * blockDim.x) >> 5;

    float4 u4 = reinterpret_cast<const float4*>(g_u)[sub];
    float4 v4 = reinterpret_cast<const float4*>(g_v)[sub];
    float  ql = g_q[sub];
    float  pb = g_pbdot, c0 = g_c0;
    float  tsc0 = g_terrsc[0], tsc1 = g_terrsc[1];

    float4 ap = make_float4(0.f, 0.f, 0.f, 0.f);  // sum tile_pos (4 dims)
    float4 ac = make_float4(0.f, 0.f, 0.f, 0.f);  // sum count_t * pte
    float  an = 0.f;                              // nation totals (nation=sub)
    float  tc0 = 0.f, tc1 = 0.f;                  // terrain counts

    const float4* __restrict__ tp_base = reinterpret_cast<const float4*>(tile_pos_emb);
    const float4* __restrict__ pe_base = reinterpret_cast<const float4*>(piece_tile_emb);

    for (int base = gwid * 8; base < T; base += nw * 8) {
        float4 tp[4], pe[4];
        float  cf[4];
        bool   val[4];

        #pragma unroll
        for (int i = 0; i < 4; i++) {
            int t = base + 2 * i + half;
            val[i] = (t < T);
            int tt = val[i] ? t : base;
            int row = tile_idxs[tt];                 // broadcast per half
            tp[i] = tp_base[row * 16 + sub];
            pe[i] = pe_base[tt * 16 + sub];
            cf[i] = (float)g_counts[tt * NNAT + sub];
        }
        #pragma unroll
        for (int i = 0; i < 4; i++) {
            if (!val[i]) {
                tp[i] = make_float4(0.f, 0.f, 0.f, 0.f);
                pe[i] = make_float4(0.f, 0.f, 0.f, 0.f);
                cf[i] = 0.f;
            }
        }

        float s1[4], s2[4], s3[4];
        #pragma unroll
        for (int i = 0; i < 4; i++) {
            s1[i] = tp[i].x * u4.x + tp[i].y * u4.y + tp[i].z * u4.z + tp[i].w * u4.w
                  + cf[i] * ql;
            s2[i] = pe[i].x * v4.x + pe[i].y * v4.y + pe[i].z * v4.z + pe[i].w * v4.w;
            s3[i] = cf[i];
            ap.x += tp[i].x; ap.y += tp[i].y; ap.z += tp[i].z; ap.w += tp[i].w;
            an += cf[i];
        }

        // 16-lane butterfly within each half (offsets < 16 stay in-half).
        #pragma unroll
        for (int o = 8; o > 0; o >>= 1) {
            #pragma unroll
            for (int i = 0; i < 4; i++) {
                s1[i] += __shfl_xor_sync(0xffffffffu, s1[i], o);
                s2[i] += __shfl_xor_sync(0xffffffffu, s2[i], o);
                s3[i] += __shfl_xor_sync(0xffffffffu, s3[i], o);
            }
        }

        #pragma unroll
        for (int i = 0; i < 4; i++) {
            ac.x += s3[i] * pe[i].x; ac.y += s3[i] * pe[i].y;
            ac.z += s3[i] * pe[i].z; ac.w += s3[i] * pe[i].w;
        }

        if (sub == 0) {
            #pragma unroll
            for (int i = 0; i < 4; i++) {
                int t = base + 2 * i + half;
                if (val[i]) {
                    int e = terrain[t] - 1;
                    out[t] = s1[i] + (e == 0 ? tsc0 : tsc1)
                           + s3[i] * (s2[i] + pb) + c0;
                    if (e == 0) tc0 += 1.f; else tc1 += 1.f;
                }
            }
        }
    }

    atomicAdd(&g_acc[4 * sub + 0],      ap.x);
    atomicAdd(&g_acc[4 * sub + 1],      ap.y);
    atomicAdd(&g_acc[4 * sub + 2],      ap.z);
    atomicAdd(&g_acc[4 * sub + 3],      ap.w);
    atomicAdd(&g_acc[64 + 4 * sub + 0], ac.x);
    atomicAdd(&g_acc[64 + 4 * sub + 1], ac.y);
    atomicAdd(&g_acc[64 + 4 * sub + 2], ac.z);
    atomicAdd(&g_acc[64 + 4 * sub + 3], ac.w);
    atomicAdd(&g_acc[128 + sub], an);
    if (sub == 0) {
        atomicAdd(&g_acc[144], tc0);
        atomicAdd(&g_acc[145], tc1);
    }

    // ---- last-block epilogue (pooled mean -> value MLP) ----
    __threadfence();
    __syncthreads();
    __shared__ bool isLast;
    if (threadIdx.x == 0)
        isLast = (atomicAdd(&g_done, 1u) == gridDim.x - 1);
    __syncthreads();
    if (!isLast) return;

    __shared__ float part[4][64];
    __shared__ float pooled[64];
    __shared__ float h[64];
    int tid = threadIdx.x;
    int c = tid >> 6;       // k-chunk 0..3
    int j = tid & 63;       // output dim
    float fT = (float)T;

    float s = 0.f;
    for (int k = c * 16; k < c * 16 + 16; k++) {
        s += g_acc[k]      * tile_fc_w[k * 64 + j];
        s += g_acc[64 + k] * piece_fc_w[(64 + k) * 64 + j];
    }
    if (c == 0) {
        for (int n = 0; n < 16; n++) s += g_acc[128 + n] * g_nproj[n * 64 + j];
        s += g_acc[144] * g_tproj[j] + g_acc[145] * g_tproj[64 + j];
        int an_ = active_nation[0];
        s += fT * tile_fc_b[j] + (float)P * piece_fc_b[j]
           + fT * nation_emb[an_ * 64 + j];
    }
    part[c][j] = s;
    __syncthreads();
    if (c == 0)
        pooled[j] = (part[0][j] + part[1][j] + part[2][j] + part[3][j]) / fT;
    __syncthreads();

    float hv = 0.f;
    for (int k = c * 16; k < c * 16 + 16; k++)
        hv += pooled[k] * value_w1[k * 64 + j];
    part[c][j] = hv;
    __syncthreads();
    if (c == 0) {
        float x = part[0][j] + part[1][j] + part[2][j] + part[3][j] + value_b1[j];
        h[j] = x > 0.f ? x : 0.f;
    }
    __syncthreads();

    if (tid < 32) {
        float v = h[tid] * value_w2[tid] + h[tid + 32] * value_w2[tid + 32];
        #pragma unroll
        for (int o = 16; o > 0; o >>= 1)
            v += __shfl_xor_sync(0xffffffffu, v, o);
        if (tid == 0) {
            out[T]     = end_turn_logit[0];
            out[T + 1] = v + value_b2[0];
        }
    }
}

extern "C" void kernel_launch(void* const* d_in, const int* in_sizes, int n_in,
                              void* d_out, int out_size)
{
    const int*   tile_idxs      = (const int*)  d_in[0];
    const int*   terrain        = (const int*)  d_in[1];
    const int*   nation_idxs    = (const int*)  d_in[2];
    const int*   piece_tidx     = (const int*)  d_in[3];
    const int*   active         = (const int*)  d_in[4];
    const float* tile_pos_emb   = (const float*)d_in[5];
    const float* terrain_emb    = (const float*)d_in[6];
    const float* nation_emb     = (const float*)d_in[7];
    const float* piece_tile_emb = (const float*)d_in[8];
    const float* tile_fc_w      = (const float*)d_in[9];
    const float* tile_fc_b      = (const float*)d_in[10];
    const float* piece_fc_w     = (const float*)d_in[11];
    const float* piece_fc_b     = (const float*)d_in[12];
    const float* tile_policy_w  = (const float*)d_in[13];
    const float* tile_policy_b  = (const float*)d_in[14];
    const float* end_turn       = (const float*)d_in[15];
    const float* value_w1       = (const float*)d_in[16];
    const float* value_b1       = (const float*)d_in[17];
    const float* value_w2       = (const float*)d_in[18];
    const float* value_b2       = (const float*)d_in[19];
    float* out = (float*)d_out;

    int T = in_sizes[0];   // 200000
    int P = in_sizes[2];   // 1000000

    k_zero_pre<<<593, 256>>>(T * NNAT,
                             tile_fc_w, tile_fc_b, piece_fc_w, piece_fc_b,
                             tile_policy_w, tile_policy_b, nation_emb, terrain_emb,
                             active);

    k_hist<<<((P >> 2) + 255) / 256, 256>>>(nation_idxs, piece_tidx, P);

    k_tiles<<<444, 256>>>(tile_idxs, terrain, tile_pos_emb, piece_tile_emb, out,
                          T, P,
                          tile_fc_w, tile_fc_b, piece_fc_w, piece_fc_b,
                          nation_emb, active,
                          value_w1, value_b1, value_w2, value_b2, end_turn);
}

// round 6
// speedup vs baseline: 1.9129x; 1.9129x over previous
#include <cuda_runtime.h>

#define NNAT 16
#define MAX_TILES 200000

// Per-tile accumulators written by k_hist: .x = sum over pieces of (q[nation]+pb), .y = piece count
__device__ float2 g_tc[MAX_TILES];
// [0,64): sum tile_pos; [64,128): sum count_t*pte; [128,144): nation totals; [144,146): terrain counts
__device__ float g_acc[160];
__device__ float g_u[64];          // W_tile_top @ policy_w
__device__ float g_v[64];          // W_piece_bot @ policy_w
__device__ float g_q[16];          // (nation_emb @ W_piece_top) @ policy_w
__device__ float g_terrsc[2];      // (terrain_emb @ W_tile_bot) @ policy_w
__device__ float g_nproj[16 * 64]; // nation_emb @ W_piece_top
__device__ float g_tproj[2 * 64];  // terrain_emb @ W_tile_bot
__device__ float g_c0;             // (tile_fc_b + nation_emb[active]) . w + policy_b
__device__ float g_pbdot;          // piece_fc_b . w

#define ZB 128   // zero blocks; block ZB does the parameter folding

__global__ void k_init(const float* __restrict__ tile_fc_w,
                       const float* __restrict__ tile_fc_b,
                       const float* __restrict__ piece_fc_w,
                       const float* __restrict__ piece_fc_b,
                       const float* __restrict__ tile_policy_w,
                       const float* __restrict__ tile_policy_b,
                       const float* __restrict__ nation_emb,
                       const float* __restrict__ terrain_emb,
                       const int*   __restrict__ active_nation,
                       int T)
{
    if (blockIdx.x < ZB) {
        // zero g_tc (T float2 = T/2 int4) and g_acc with wide stores
        int4* p = reinterpret_cast<int4*>(g_tc);
        int n4 = T / 2;                      // T even
        int i = blockIdx.x * blockDim.x + threadIdx.x;
        int stride = ZB * blockDim.x;
        int4 z = make_int4(0, 0, 0, 0);
        for (int k = i; k < n4; k += stride) p[k] = z;
        if (i < 160) g_acc[i] = 0.f;
        return;
    }

    // ---- parameter folding block (256 threads) ----
    __shared__ float w[64];
    int tid = threadIdx.x;
    if (tid < 64) w[tid] = tile_policy_w[tid];
    __syncthreads();

    #pragma unroll
    for (int r = 0; r < 4; r++) {
        int idx = tid + 256 * r;        // 0..1023
        int n = idx >> 6, j = idx & 63;
        float s = 0.f;
        for (int k = 0; k < 64; k++)
            s += nation_emb[n * 64 + k] * piece_fc_w[k * 64 + j];
        g_nproj[idx] = s;
    }

    if (tid < 64) {
        float s = 0.f;
        for (int c = 0; c < 64; c++) s += tile_fc_w[tid * 64 + c] * w[c];
        g_u[tid] = s;
    } else if (tid < 128) {
        int j = tid - 64;
        float s = 0.f;
        for (int c = 0; c < 64; c++) s += piece_fc_w[(64 + j) * 64 + c] * w[c];
        g_v[j] = s;
    } else {
        int idx = tid - 128;            // 0..127
        int e = idx >> 6, j = idx & 63;
        float s = 0.f;
        for (int k = 0; k < 64; k++)
            s += terrain_emb[e * 64 + k] * tile_fc_w[(64 + k) * 64 + j];
        g_tproj[idx] = s;
    }
    __syncthreads();

    if (tid < 16) {
        float s = 0.f;
        for (int c = 0; c < 64; c++) s += g_nproj[tid * 64 + c] * w[c];
        g_q[tid] = s;
    } else if (tid < 18) {
        int e = tid - 16;
        float s = 0.f;
        for (int c = 0; c < 64; c++) s += g_tproj[e * 64 + c] * w[c];
        g_terrsc[e] = s;
    } else if (tid == 18) {
        float s = 0.f;
        for (int c = 0; c < 64; c++) s += piece_fc_b[c] * w[c];
        g_pbdot = s;
    } else if (tid == 19) {
        int an = active_nation[0];
        float s = 0.f;
        for (int c = 0; c < 64; c++)
            s += (tile_fc_b[c] + nation_emb[an * 64 + c]) * w[c];
        g_c0 = s + tile_policy_b[0];
    }
}

// Per piece: g_tc[t] += {q[n]+pb, 1}; per-nation totals via smem histogram.
__global__ void k_hist(const int* __restrict__ nation_idxs,
                       const int* __restrict__ piece_tile_idxs,
                       int P)
{
    __shared__ unsigned int sh[NNAT];
    __shared__ float sq[NNAT];
    int tid = threadIdx.x;
    if (tid < NNAT) { sh[tid] = 0u; sq[tid] = g_q[tid] + g_pbdot; }
    __syncthreads();

    int i = blockIdx.x * blockDim.x + tid;
    int P4 = P >> 2;
    if (i < P4) {
        int4 n4 = reinterpret_cast<const int4*>(nation_idxs)[i];
        int4 t4 = reinterpret_cast<const int4*>(piece_tile_idxs)[i];
        atomicAdd(&g_tc[t4.x].x, sq[n4.x]); atomicAdd(&g_tc[t4.x].y, 1.f);
        atomicAdd(&g_tc[t4.y].x, sq[n4.y]); atomicAdd(&g_tc[t4.y].y, 1.f);
        atomicAdd(&g_tc[t4.z].x, sq[n4.z]); atomicAdd(&g_tc[t4.z].y, 1.f);
        atomicAdd(&g_tc[t4.w].x, sq[n4.w]); atomicAdd(&g_tc[t4.w].y, 1.f);
        atomicAdd(&sh[n4.x], 1u); atomicAdd(&sh[n4.y], 1u);
        atomicAdd(&sh[n4.z], 1u); atomicAdd(&sh[n4.w], 1u);
    }
    int rem = P - P4 * 4;
    if (i < rem) {
        int idx = P4 * 4 + i;
        int t = piece_tile_idxs[idx], n = nation_idxs[idx];
        atomicAdd(&g_tc[t].x, sq[n]); atomicAdd(&g_tc[t].y, 1.f);
        atomicAdd(&sh[n], 1u);
    }
    __syncthreads();
    if (tid < NNAT) atomicAdd(&g_acc[128 + tid], (float)sh[tid]);
}

// Warp-per-tile, U=6 unroll. Two 5-level butterflies per tile (pos-dot, pte-dot);
// piece count/q-sum arrive as an 8B broadcast load from g_tc.
__global__ void k_tiles(const int*   __restrict__ tile_idxs,
                        const int*   __restrict__ terrain,
                        const float* __restrict__ tile_pos_emb,
                        const float* __restrict__ piece_tile_emb,
                        float*       __restrict__ out,
                        int T)
{
    const int U = 6;
    int lane = threadIdx.x & 31;
    int gwid = (blockIdx.x * blockDim.x + threadIdx.x) >> 5;
    int nw   = (gridDim.x * blockDim.x) >> 5;

    float u0 = g_u[2 * lane], u1 = g_u[2 * lane + 1];
    float v0 = g_v[2 * lane], v1 = g_v[2 * lane + 1];
    float c0 = g_c0;
    float tsc0 = g_terrsc[0], tsc1 = g_terrsc[1];

    float ap0 = 0.f, ap1 = 0.f;   // sum tile_pos (this lane's 2 dims)
    float ac0 = 0.f, ac1 = 0.f;   // sum count_t * pte
    float tc0 = 0.f, tc1 = 0.f;   // terrain counts (lane 0)

    const float2* __restrict__ tp_base = reinterpret_cast<const float2*>(tile_pos_emb);
    const float2* __restrict__ pe_base = reinterpret_cast<const float2*>(piece_tile_emb);

    for (int base = gwid * U; base < T; base += nw * U) {
        float2 tp[U], pe[U], tc[U];
        bool   val[U];

        #pragma unroll
        for (int i = 0; i < U; i++) {
            int t = base + i;
            val[i] = (t < T);
            int tt = val[i] ? t : base;
            int row = tile_idxs[tt];
            tp[i] = tp_base[row * 32 + lane];
            pe[i] = pe_base[tt * 32 + lane];
            tc[i] = g_tc[tt];                 // broadcast 8B
        }
        #pragma unroll
        for (int i = 0; i < U; i++) {
            if (!val[i]) {
                tp[i] = make_float2(0.f, 0.f);
                pe[i] = make_float2(0.f, 0.f);
                tc[i] = make_float2(0.f, 0.f);
            }
        }

        float s1[U], s2[U];
        #pragma unroll
        for (int i = 0; i < U; i++) {
            s1[i] = tp[i].x * u0 + tp[i].y * u1;
            s2[i] = pe[i].x * v0 + pe[i].y * v1;
            ap0 += tp[i].x; ap1 += tp[i].y;
            ac0 += tc[i].y * pe[i].x; ac1 += tc[i].y * pe[i].y;
        }

        #pragma unroll
        for (int o = 16; o > 0; o >>= 1) {
            #pragma unroll
            for (int i = 0; i < U; i++) {
                s1[i] += __shfl_xor_sync(0xffffffffu, s1[i], o);
                s2[i] += __shfl_xor_sync(0xffffffffu, s2[i], o);
            }
        }

        if (lane == 0) {
            #pragma unroll
            for (int i = 0; i < U; i++) {
                if (val[i]) {
                    int t = base + i;
                    int e = terrain[t] - 1;
                    out[t] = s1[i] + (e == 0 ? tsc0 : tsc1)
                           + tc[i].y * s2[i] + tc[i].x + c0;
                    if (e == 0) tc0 += 1.f; else tc1 += 1.f;
                }
            }
        }
    }

    atomicAdd(&g_acc[2 * lane],          ap0);
    atomicAdd(&g_acc[2 * lane + 1],      ap1);
    atomicAdd(&g_acc[64 + 2 * lane],     ac0);
    atomicAdd(&g_acc[64 + 2 * lane + 1], ac1);
    if (lane == 0) {
        atomicAdd(&g_acc[144], tc0);
        atomicAdd(&g_acc[145], tc1);
    }
}

// Parallel epilogue: 256 threads, 4 k-chunks of 16, smem reduce.
__global__ void k_final(const float* __restrict__ tile_fc_w,
                        const float* __restrict__ tile_fc_b,
                        const float* __restrict__ piece_fc_w,
                        const float* __restrict__ piece_fc_b,
                        const float* __restrict__ nation_emb,
                        const int*   __restrict__ active_nation,
                        const float* __restrict__ value_w1,
                        const float* __restrict__ value_b1,
                        const float* __restrict__ value_w2,
                        const float* __restrict__ value_b2,
                        const float* __restrict__ end_turn_logit,
                        float*       __restrict__ out,
                        int T, int P)
{
    __shared__ float part[4][64];
    __shared__ float pooled[64];
    __shared__ float h[64];
    int tid = threadIdx.x;
    int c = tid >> 6;       // k-chunk 0..3
    int j = tid & 63;       // output dim
    float fT = (float)T;

    float s = 0.f;
    for (int k = c * 16; k < c * 16 + 16; k++) {
        s += g_acc[k]      * tile_fc_w[k * 64 + j];
        s += g_acc[64 + k] * piece_fc_w[(64 + k) * 64 + j];
    }
    {
        // spread the small extras across chunks: chunk c handles nations 4c..4c+3
        for (int n = c * 4; n < c * 4 + 4; n++)
            s += g_acc[128 + n] * g_nproj[n * 64 + j];
    }
    if (c == 0) {
        s += g_acc[144] * g_tproj[j] + g_acc[145] * g_tproj[64 + j];
        int an_ = active_nation[0];
        s += fT * tile_fc_b[j] + (float)P * piece_fc_b[j]
           + fT * nation_emb[an_ * 64 + j];
    }
    part[c][j] = s;
    __syncthreads();
    if (c == 0)
        pooled[j] = (part[0][j] + part[1][j] + part[2][j] + part[3][j]) / fT;
    __syncthreads();

    float hv = 0.f;
    for (int k = c * 16; k < c * 16 + 16; k++)
        hv += pooled[k] * value_w1[k * 64 + j];
    part[c][j] = hv;
    __syncthreads();
    if (c == 0) {
        float x = part[0][j] + part[1][j] + part[2][j] + part[3][j] + value_b1[j];
        h[j] = x > 0.f ? x : 0.f;
    }
    __syncthreads();

    if (tid < 32) {
        float v = h[tid] * value_w2[tid] + h[tid + 32] * value_w2[tid + 32];
        #pragma unroll
        for (int o = 16; o > 0; o >>= 1)
            v += __shfl_xor_sync(0xffffffffu, v, o);
        if (tid == 0) {
            out[T]     = end_turn_logit[0];
            out[T + 1] = v + value_b2[0];
        }
    }
}

extern "C" void kernel_launch(void* const* d_in, const int* in_sizes, int n_in,
                              void* d_out, int out_size)
{
    const int*   tile_idxs      = (const int*)  d_in[0];
    const int*   terrain        = (const int*)  d_in[1];
    const int*   nation_idxs    = (const int*)  d_in[2];
    const int*   piece_tidx     = (const int*)  d_in[3];
    const int*   active         = (const int*)  d_in[4];
    const float* tile_pos_emb   = (const float*)d_in[5];
    const float* terrain_emb    = (const float*)d_in[6];
    const float* nation_emb     = (const float*)d_in[7];
    const float* piece_tile_emb = (const float*)d_in[8];
    const float* tile_fc_w      = (const float*)d_in[9];
    const float* tile_fc_b      = (const float*)d_in[10];
    const float* piece_fc_w     = (const float*)d_in[11];
    const float* piece_fc_b     = (const float*)d_in[12];
    const float* tile_policy_w  = (const float*)d_in[13];
    const float* tile_policy_b  = (const float*)d_in[14];
    const float* end_turn       = (const float*)d_in[15];
    const float* value_w1       = (const float*)d_in[16];
    const float* value_b1       = (const float*)d_in[17];
    const float* value_w2       = (const float*)d_in[18];
    const float* value_b2       = (const float*)d_in[19];
    float* out = (float*)d_out;

    int T = in_sizes[0];   // 200000
    int P = in_sizes[2];   // 1000000

    k_init<<<ZB + 1, 256>>>(tile_fc_w, tile_fc_b, piece_fc_w, piece_fc_b,
                            tile_policy_w, tile_policy_b, nation_emb, terrain_emb,
                            active, T);

    k_hist<<<((P >> 2) + 255) / 256, 256>>>(nation_idxs, piece_tidx, P);

    k_tiles<<<592, 256>>>(tile_idxs, terrain, tile_pos_emb, piece_tile_emb, out, T);

    k_final<<<1, 256>>>(tile_fc_w, tile_fc_b, piece_fc_w, piece_fc_b,
                        nation_emb, active,
                        value_w1, value_b1, value_w2, value_b2,
                        end_turn, out, T, P);
}

// round 8
// speedup vs baseline: 1.9744x; 1.0321x over previous
#include <cuda_runtime.h>

#define NNAT 16
#define MAX_TILES 200000

// Per-tile packed accumulator written by k_hist:
//   bits [42:64) = piece count
//   bits [0:42)  = sum over pieces of (q[nation]+pb+4.0) in fixed point, scale 2^30
__device__ unsigned long long g_tcu[MAX_TILES];
// [0,64): sum tile_pos; [64,128): sum count_t*pte; [128,144): nation totals; [144,146): terrain counts
__device__ float g_acc[160];
__device__ float g_u[64];          // W_tile_top @ policy_w
__device__ float g_v[64];          // W_piece_bot @ policy_w
__device__ float g_q[16];          // (nation_emb @ W_piece_top) @ policy_w
__device__ float g_terrsc[2];      // (terrain_emb @ W_tile_bot) @ policy_w
__device__ float g_nproj[16 * 64]; // nation_emb @ W_piece_top
__device__ float g_tproj[2 * 64];  // terrain_emb @ W_tile_bot
__device__ float g_c0;             // (tile_fc_b + nation_emb[active]) . w + policy_b
__device__ float g_pbdot;          // piece_fc_b . w
__device__ unsigned int g_done;    // last-block epilogue counter

#define ZB 128          // zero blocks; block ZB does the parameter folding
#define QSCALE 1073741824.0f   // 2^30
#define QOFF   4.0f
#define CNT_SHIFT 42

__global__ void k_init(const float* __restrict__ tile_fc_w,
                       const float* __restrict__ tile_fc_b,
                       const float* __restrict__ piece_fc_w,
                       const float* __restrict__ piece_fc_b,
                       const float* __restrict__ tile_policy_w,
                       const float* __restrict__ tile_policy_b,
                       const float* __restrict__ nation_emb,
                       const float* __restrict__ terrain_emb,
                       const int*   __restrict__ active_nation,
                       int T)
{
    if (blockIdx.x < ZB) {
        // zero g_tcu (T ull = T/2 int4) and g_acc with wide stores
        int4* p = reinterpret_cast<int4*>(g_tcu);
        int n4 = T / 2;                      // T even
        int i = blockIdx.x * blockDim.x + threadIdx.x;
        int stride = ZB * blockDim.x;
        int4 z = make_int4(0, 0, 0, 0);
        for (int k = i; k < n4; k += stride) p[k] = z;
        if (i < 160) g_acc[i] = 0.f;
        if (i == 160) g_done = 0u;
        return;
    }

    // ---- parameter folding block (256 threads) ----
    __shared__ float w[64];
    int tid = threadIdx.x;
    if (tid < 64) w[tid] = tile_policy_w[tid];
    __syncthreads();

    #pragma unroll
    for (int r = 0; r < 4; r++) {
        int idx = tid + 256 * r;        // 0..1023
        int n = idx >> 6, j = idx & 63;
        float s = 0.f;
        #pragma unroll 16
        for (int k = 0; k < 64; k++)
            s += nation_emb[n * 64 + k] * piece_fc_w[k * 64 + j];
        g_nproj[idx] = s;
    }

    if (tid < 64) {
        float s = 0.f;
        #pragma unroll 16
        for (int c = 0; c < 64; c++) s += tile_fc_w[tid * 64 + c] * w[c];
        g_u[tid] = s;
    } else if (tid < 128) {
        int j = tid - 64;
        float s = 0.f;
        #pragma unroll 16
        for (int c = 0; c < 64; c++) s += piece_fc_w[(64 + j) * 64 + c] * w[c];
        g_v[j] = s;
    } else {
        int idx = tid - 128;            // 0..127
        int e = idx >> 6, j = idx & 63;
        float s = 0.f;
        #pragma unroll 16
        for (int k = 0; k < 64; k++)
            s += terrain_emb[e * 64 + k] * tile_fc_w[(64 + k) * 64 + j];
        g_tproj[idx] = s;
    }
    __syncthreads();

    if (tid < 16) {
        float s = 0.f;
        for (int c = 0; c < 64; c++) s += g_nproj[tid * 64 + c] * w[c];
        g_q[tid] = s;
    } else if (tid < 18) {
        int e = tid - 16;
        float s = 0.f;
        for (int c = 0; c < 64; c++) s += g_tproj[e * 64 + c] * w[c];
        g_terrsc[e] = s;
    } else if (tid == 18) {
        float s = 0.f;
        for (int c = 0; c < 64; c++) s += piece_fc_b[c] * w[c];
        g_pbdot = s;
    } else if (tid == 19) {
        int an = active_nation[0];
        float s = 0.f;
        for (int c = 0; c < 64; c++)
            s += (tile_fc_b[c] + nation_emb[an * 64 + c]) * w[c];
        g_c0 = s + tile_policy_b[0];
    }
}

// Per piece: single 64-bit packed atomic into g_tcu[t]; per-nation totals via smem histogram.
__global__ void k_hist(const int* __restrict__ nation_idxs,
                       const int* __restrict__ piece_tile_idxs,
                       int P)
{
    __shared__ unsigned int sh[NNAT];
    __shared__ unsigned long long sq[NNAT];
    int tid = threadIdx.x;
    if (tid < NNAT) {
        sh[tid] = 0u;
        float qv = g_q[tid] + g_pbdot + QOFF;   // positive, ~4.0
        sq[tid] = (unsigned long long)llroundf(qv * QSCALE)
                + (1ULL << CNT_SHIFT);
    }
    __syncthreads();

    int i = blockIdx.x * blockDim.x + tid;
    int P4 = P >> 2;
    if (i < P4) {
        int4 n4 = reinterpret_cast<const int4*>(nation_idxs)[i];
        int4 t4 = reinterpret_cast<const int4*>(piece_tile_idxs)[i];
        atomicAdd(&g_tcu[t4.x], sq[n4.x]);
        atomicAdd(&g_tcu[t4.y], sq[n4.y]);
        atomicAdd(&g_tcu[t4.z], sq[n4.z]);
        atomicAdd(&g_tcu[t4.w], sq[n4.w]);
        atomicAdd(&sh[n4.x], 1u); atomicAdd(&sh[n4.y], 1u);
        atomicAdd(&sh[n4.z], 1u); atomicAdd(&sh[n4.w], 1u);
    }
    int rem = P - P4 * 4;
    if (i < rem) {
        int idx = P4 * 4 + i;
        atomicAdd(&g_tcu[piece_tile_idxs[idx]], sq[nation_idxs[idx]]);
        atomicAdd(&sh[nation_idxs[idx]], 1u);
    }
    __syncthreads();
    if (tid < NNAT) atomicAdd(&g_acc[128 + tid], (float)sh[tid]);
}

// Warp-per-tile, U=6 unroll; two 5-level butterflies per tile.
// Last block to finish runs the pooled/value epilogue inline.
__global__ void k_tiles(const int*   __restrict__ tile_idxs,
                        const int*   __restrict__ terrain,
                        const float* __restrict__ tile_pos_emb,
                        const float* __restrict__ piece_tile_emb,
                        float*       __restrict__ out,
                        int T, int P,
                        const float* __restrict__ tile_fc_w,
                        const float* __restrict__ tile_fc_b,
                        const float* __restrict__ piece_fc_w,
                        const float* __restrict__ piece_fc_b,
                        const float* __restrict__ nation_emb,
                        const int*   __restrict__ active_nation,
                        const float* __restrict__ value_w1,
                        const float* __restrict__ value_b1,
                        const float* __restrict__ value_w2,
                        const float* __restrict__ value_b2,
                        const float* __restrict__ end_turn_logit)
{
    const int U = 6;
    int lane = threadIdx.x & 31;
    int gwid = (blockIdx.x * blockDim.x + threadIdx.x) >> 5;
    int nw   = (gridDim.x * blockDim.x) >> 5;

    float u0 = g_u[2 * lane], u1 = g_u[2 * lane + 1];
    float v0 = g_v[2 * lane], v1 = g_v[2 * lane + 1];
    float c0 = g_c0;
    float tsc0 = g_terrsc[0], tsc1 = g_terrsc[1];

    float ap0 = 0.f, ap1 = 0.f;   // sum tile_pos (this lane's 2 dims)
    float ac0 = 0.f, ac1 = 0.f;   // sum count_t * pte
    float tcc0 = 0.f, tcc1 = 0.f; // terrain counts (lane 0)

    const float2* __restrict__ tp_base = reinterpret_cast<const float2*>(tile_pos_emb);
    const float2* __restrict__ pe_base = reinterpret_cast<const float2*>(piece_tile_emb);

    for (int base = gwid * U; base < T; base += nw * U) {
        float2 tp[U], pe[U];
        unsigned long long pk[U];
        bool   val[U];

        #pragma unroll
        for (int i = 0; i < U; i++) {
            int t = base + i;
            val[i] = (t < T);
            int tt = val[i] ? t : base;
            int row = tile_idxs[tt];
            tp[i] = tp_base[row * 32 + lane];
            pe[i] = pe_base[tt * 32 + lane];
            pk[i] = g_tcu[tt];                // broadcast 8B
        }

        float cnt[U], qs[U];
        #pragma unroll
        for (int i = 0; i < U; i++) {
            if (!val[i]) {
                tp[i] = make_float2(0.f, 0.f);
                pe[i] = make_float2(0.f, 0.f);
                pk[i] = 0ull;
            }
            cnt[i] = (float)(unsigned int)(pk[i] >> CNT_SHIFT);
            qs[i]  = (float)(long long)(pk[i] & ((1ULL << CNT_SHIFT) - 1ull))
                     * (1.0f / QSCALE) - cnt[i] * QOFF;
        }

        float s1[U], s2[U];
        #pragma unroll
        for (int i = 0; i < U; i++) {
            s1[i] = tp[i].x * u0 + tp[i].y * u1;
            s2[i] = pe[i].x * v0 + pe[i].y * v1;
            ap0 += tp[i].x; ap1 += tp[i].y;
            ac0 += cnt[i] * pe[i].x; ac1 += cnt[i] * pe[i].y;
        }

        #pragma unroll
        for (int o = 16; o > 0; o >>= 1) {
            #pragma unroll
            for (int i = 0; i < U; i++) {
                s1[i] += __shfl_xor_sync(0xffffffffu, s1[i], o);
                s2[i] += __shfl_xor_sync(0xffffffffu, s2[i], o);
            }
        }

        if (lane == 0) {
            #pragma unroll
            for (int i = 0; i < U; i++) {
                if (val[i]) {
                    int t = base + i;
                    int e = terrain[t] - 1;
                    out[t] = s1[i] + (e == 0 ? tsc0 : tsc1)
                           + cnt[i] * s2[i] + qs[i] + c0;
                    if (e == 0) tcc0 += 1.f; else tcc1 += 1.f;
                }
            }
        }
    }

    atomicAdd(&g_acc[2 * lane],          ap0);
    atomicAdd(&g_acc[2 * lane + 1],      ap1);
    atomicAdd(&g_acc[64 + 2 * lane],     ac0);
    atomicAdd(&g_acc[64 + 2 * lane + 1], ac1);
    if (lane == 0) {
        atomicAdd(&g_acc[144], tcc0);
        atomicAdd(&g_acc[145], tcc1);
    }

    // ---- last-block epilogue (pooled mean -> value MLP) ----
    __threadfence();
    __syncthreads();
    __shared__ bool isLast;
    if (threadIdx.x == 0)
        isLast = (atomicAdd(&g_done, 1u) == gridDim.x - 1);
    __syncthreads();
    if (!isLast) return;

    __shared__ float part[4][64];
    __shared__ float pooled[64];
    __shared__ float h[64];
    int tid = threadIdx.x;
    int c = tid >> 6;       // k-chunk 0..3
    int j = tid & 63;       // output dim
    float fT = (float)T;

    float s = 0.f;
    #pragma unroll 16
    for (int k = c * 16; k < c * 16 + 16; k++) {
        s += g_acc[k]      * tile_fc_w[k * 64 + j];
        s += g_acc[64 + k] * piece_fc_w[(64 + k) * 64 + j];
    }
    #pragma unroll 4
    for (int n = c * 4; n < c * 4 + 4; n++)
        s += g_acc[128 + n] * g_nproj[n * 64 + j];
    if (c == 0) {
        s += g_acc[144] * g_tproj[j] + g_acc[145] * g_tproj[64 + j];
        int an_ = active_nation[0];
        s += fT * tile_fc_b[j] + (float)P * piece_fc_b[j]
           + fT * nation_emb[an_ * 64 + j];
    }
    part[c][j] = s;
    __syncthreads();
    if (c == 0)
        pooled[j] = (part[0][j] + part[1][j] + part[2][j] + part[3][j]) / fT;
    __syncthreads();

    float hv = 0.f;
    #pragma unroll 16
    for (int k = c * 16; k < c * 16 + 16; k++)
        hv += pooled[k] * value_w1[k * 64 + j];
    part[c][j] = hv;
    __syncthreads();
    if (c == 0) {
        float x = part[0][j] + part[1][j] + part[2][j] + part[3][j] + value_b1[j];
        h[j] = x > 0.f ? x : 0.f;
    }
    __syncthreads();

    if (tid < 32) {
        float v = h[tid] * value_w2[tid] + h[tid + 32] * value_w2[tid + 32];
        #pragma unroll
        for (int o = 16; o > 0; o >>= 1)
            v += __shfl_xor_sync(0xffffffffu, v, o);
        if (tid == 0) {
            out[T]     = end_turn_logit[0];
            out[T + 1] = v + value_b2[0];
        }
    }
}

extern "C" void kernel_launch(void* const* d_in, const int* in_sizes, int n_in,
                              void* d_out, int out_size)
{
    const int*   tile_idxs      = (const int*)  d_in[0];
    const int*   terrain        = (const int*)  d_in[1];
    const int*   nation_idxs    = (const int*)  d_in[2];
    const int*   piece_tidx     = (const int*)  d_in[3];
    const int*   active         = (const int*)  d_in[4];
    const float* tile_pos_emb   = (const float*)d_in[5];
    const float* terrain_emb    = (const float*)d_in[6];
    const float* nation_emb     = (const float*)d_in[7];
    const float* piece_tile_emb = (const float*)d_in[8];
    const float* tile_fc_w      = (const float*)d_in[9];
    const float* tile_fc_b      = (const float*)d_in[10];
    const float* piece_fc_w     = (const float*)d_in[11];
    const float* piece_fc_b     = (const float*)d_in[12];
    const float* tile_policy_w  = (const float*)d_in[13];
    const float* tile_policy_b  = (const float*)d_in[14];
    const float* end_turn       = (const float*)d_in[15];
    const float* value_w1       = (const float*)d_in[16];
    const float* value_b1       = (const float*)d_in[17];
    const float* value_w2       = (const float*)d_in[18];
    const float* value_b2       = (const float*)d_in[19];
    float* out = (float*)d_out;

    int T = in_sizes[0];   // 200000
    int P = in_sizes[2];   // 1000000

    k_init<<<ZB + 1, 256>>>(tile_fc_w, tile_fc_b, piece_fc_w, piece_fc_b,
                            tile_policy_b ? tile_policy_w : tile_policy_w,
                            tile_policy_b, nation_emb, terrain_emb,
                            active, T);

    k_hist<<<((P >> 2) + 255) / 256, 256>>>(nation_idxs, piece_tidx, P);

    k_tiles<<<592, 256>>>(tile_idxs, terrain, tile_pos_emb, piece_tile_emb, out,
                          T, P,
                          tile_fc_w, tile_fc_b, piece_fc_w, piece_fc_b,
                          nation_emb, active,
                          value_w1, value_b1, value_w2, value_b2, end_turn);
}

// round 10
// speedup vs baseline: 2.0651x; 1.0459x over previous
#include <cuda_runtime.h>

#define NNAT 16
#define MAX_TILES 200000

// Per-tile packed accumulator written by k_hist:
//   bits [42:64) = piece count
//   bits [0:42)  = sum over pieces of (q[nation]+pb+4.0) in fixed point, scale 2^30
// INVARIANT: zero outside a kernel_launch invocation. k_tiles restores zeros
// after consuming (module load zero-fills initially), so no zeroing pass runs.
__device__ unsigned long long g_tcu[MAX_TILES];
// [0,64): sum tile_pos; [64,128): sum count_t*pte; [128,144): nation totals; [144,146): terrain counts
// Same invariant: epilogue zeroes after reading.
__device__ float g_acc[160];
__device__ float g_u[64];          // W_tile_top @ policy_w
__device__ float g_v[64];          // W_piece_bot @ policy_w
__device__ float g_q[16];          // (nation_emb @ W_piece_top) @ policy_w
__device__ float g_terrsc[2];      // (terrain_emb @ W_tile_bot) @ policy_w
__device__ float g_nproj[16 * 64]; // nation_emb @ W_piece_top
__device__ float g_tproj[2 * 64];  // terrain_emb @ W_tile_bot
__device__ float g_c0;             // (tile_fc_b + nation_emb[active]) . w + policy_b
__device__ float g_pbdot;          // piece_fc_b . w
__device__ unsigned int g_done;    // last-block epilogue counter (reset by epilogue)

#define QSCALE 1073741824.0f   // 2^30
#define QOFF   4.0f
#define CNT_SHIFT 42

// Parameter folding, parallelized: blocks 0..15 -> nproj row n + q[n];
// block 16 -> u, v, tproj, terrsc, pbdot, c0. 64 threads per block.
__global__ void k_pre(const float* __restrict__ tile_fc_w,
                      const float* __restrict__ tile_fc_b,
                      const float* __restrict__ piece_fc_w,
                      const float* __restrict__ piece_fc_b,
                      const float* __restrict__ tile_policy_w,
                      const float* __restrict__ tile_policy_b,
                      const float* __restrict__ nation_emb,
                      const float* __restrict__ terrain_emb,
                      const int*   __restrict__ active_nation)
{
    __shared__ float w[64];
    __shared__ float rA[64], rB[64], rC[64], rD[64];
    int j = threadIdx.x;  // 0..63
    w[j] = tile_policy_w[j];
    __syncthreads();

    int b = blockIdx.x;
    if (b < 16) {
        // nproj[b][j] = sum_k nation_emb[b][k] * piece_fc_w[k][j]
        float s = 0.f;
        #pragma unroll 16
        for (int k = 0; k < 64; k++)
            s += nation_emb[b * 64 + k] * piece_fc_w[k * 64 + j];
        g_nproj[b * 64 + j] = s;

        // q[b] = sum_j nproj[b][j] * w[j]  (reduce from registers)
        rA[j] = s * w[j];
        __syncthreads();
        if (j < 32) {
            float t = rA[j] + rA[j + 32];
            #pragma unroll
            for (int o = 16; o > 0; o >>= 1)
                t += __shfl_xor_sync(0xffffffffu, t, o);
            if (j == 0) g_q[b] = t;
        }
    } else {
        float su = 0.f, sv = 0.f, t0 = 0.f, t1 = 0.f;
        #pragma unroll 16
        for (int c = 0; c < 64; c++) {
            su += tile_fc_w[j * 64 + c] * w[c];          // u[j]
            sv += piece_fc_w[(64 + j) * 64 + c] * w[c];  // v[j]
        }
        #pragma unroll 16
        for (int k = 0; k < 64; k++) {
            float tw = tile_fc_w[(64 + k) * 64 + j];
            t0 += terrain_emb[k] * tw;                   // tproj[0][j]
            t1 += terrain_emb[64 + k] * tw;              // tproj[1][j]
        }
        g_u[j] = su;
        g_v[j] = sv;
        g_tproj[j] = t0;
        g_tproj[64 + j] = t1;

        int an = active_nation[0];
        rA[j] = t0 * w[j];
        rB[j] = t1 * w[j];
        rC[j] = piece_fc_b[j] * w[j];
        rD[j] = (tile_fc_b[j] + nation_emb[an * 64 + j]) * w[j];
        __syncthreads();
        if (j < 4) {
            const float* r = (j == 0) ? rA : (j == 1) ? rB : (j == 2) ? rC : rD;
            float s = 0.f;
            #pragma unroll 16
            for (int k = 0; k < 64; k++) s += r[k];
            if (j == 0) g_terrsc[0] = s;
            else if (j == 1) g_terrsc[1] = s;
            else if (j == 2) g_pbdot = s;
            else g_c0 = s + tile_policy_b[0];
        }
    }
}

// Per piece: single 64-bit packed atomic into g_tcu[t]; per-nation totals via smem histogram.
__global__ void k_hist(const int* __restrict__ nation_idxs,
                       const int* __restrict__ piece_tile_idxs,
                       int P)
{
    __shared__ unsigned int sh[NNAT];
    __shared__ unsigned long long sq[NNAT];
    int tid = threadIdx.x;
    if (tid < NNAT) {
        sh[tid] = 0u;
        float qv = g_q[tid] + g_pbdot + QOFF;   // positive, ~4.0
        sq[tid] = (unsigned long long)llroundf(qv * QSCALE)
                + (1ULL << CNT_SHIFT);
    }
    __syncthreads();

    int i = blockIdx.x * blockDim.x + tid;
    int P4 = P >> 2;
    if (i < P4) {
        int4 n4 = reinterpret_cast<const int4*>(nation_idxs)[i];
        int4 t4 = reinterpret_cast<const int4*>(piece_tile_idxs)[i];
        atomicAdd(&g_tcu[t4.x], sq[n4.x]);
        atomicAdd(&g_tcu[t4.y], sq[n4.y]);
        atomicAdd(&g_tcu[t4.z], sq[n4.z]);
        atomicAdd(&g_tcu[t4.w], sq[n4.w]);
        atomicAdd(&sh[n4.x], 1u); atomicAdd(&sh[n4.y], 1u);
        atomicAdd(&sh[n4.z], 1u); atomicAdd(&sh[n4.w], 1u);
    }
    int rem = P - P4 * 4;
    if (i < rem) {
        int idx = P4 * 4 + i;
        atomicAdd(&g_tcu[piece_tile_idxs[idx]], sq[nation_idxs[idx]]);
        atomicAdd(&sh[nation_idxs[idx]], 1u);
    }
    __syncthreads();
    if (tid < NNAT) atomicAdd(&g_acc[128 + tid], (float)sh[tid]);
}

// Warp-per-tile, U=6 unroll; two 5-level butterflies per tile.
// Self-cleaning: zeroes g_tcu entries after consuming them.
// Last block to finish runs the pooled/value epilogue inline and zeroes g_acc/g_done.
__global__ void k_tiles(const int*   __restrict__ tile_idxs,
                        const int*   __restrict__ terrain,
                        const float* __restrict__ tile_pos_emb,
                        const float* __restrict__ piece_tile_emb,
                        float*       __restrict__ out,
                        int T, int P,
                        const float* __restrict__ tile_fc_w,
                        const float* __restrict__ tile_fc_b,
                        const float* __restrict__ piece_fc_w,
                        const float* __restrict__ piece_fc_b,
                        const float* __restrict__ nation_emb,
                        const int*   __restrict__ active_nation,
                        const float* __restrict__ value_w1,
                        const float* __restrict__ value_b1,
                        const float* __restrict__ value_w2,
                        const float* __restrict__ value_b2,
                        const float* __restrict__ end_turn_logit)
{
    const int U = 6;
    int lane = threadIdx.x & 31;
    int gwid = (blockIdx.x * blockDim.x + threadIdx.x) >> 5;
    int nw   = (gridDim.x * blockDim.x) >> 5;

    float u0 = g_u[2 * lane], u1 = g_u[2 * lane + 1];
    float v0 = g_v[2 * lane], v1 = g_v[2 * lane + 1];
    float c0 = g_c0;
    float tsc0 = g_terrsc[0], tsc1 = g_terrsc[1];

    float ap0 = 0.f, ap1 = 0.f;   // sum tile_pos (this lane's 2 dims)
    float ac0 = 0.f, ac1 = 0.f;   // sum count_t * pte
    float tcc0 = 0.f, tcc1 = 0.f; // terrain counts (lane 0)

    const float2* __restrict__ tp_base = reinterpret_cast<const float2*>(tile_pos_emb);
    const float2* __restrict__ pe_base = reinterpret_cast<const float2*>(piece_tile_emb);

    for (int base = gwid * U; base < T; base += nw * U) {
        float2 tp[U], pe[U];
        unsigned long long pk[U];
        bool   val[U];

        #pragma unroll
        for (int i = 0; i < U; i++) {
            int t = base + i;
            val[i] = (t < T);
            int tt = val[i] ? t : base;
            int row = tile_idxs[tt];
            tp[i] = tp_base[row * 32 + lane];
            pe[i] = pe_base[tt * 32 + lane];
            pk[i] = g_tcu[tt];                // broadcast 8B
        }

        float cnt[U], qs[U];
        #pragma unroll
        for (int i = 0; i < U; i++) {
            if (!val[i]) {
                tp[i] = make_float2(0.f, 0.f);
                pe[i] = make_float2(0.f, 0.f);
                pk[i] = 0ull;
            }
            cnt[i] = (float)(unsigned int)(pk[i] >> CNT_SHIFT);
            qs[i]  = (float)(long long)(pk[i] & ((1ULL << CNT_SHIFT) - 1ull))
                     * (1.0f / QSCALE) - cnt[i] * QOFF;
        }

        // Restore zeros for the next graph replay (values already consumed
        // into registers above; this warp is the sole owner of these entries).
        if (lane == 0) {
            #pragma unroll
            for (int i = 0; i < U; i++)
                if (val[i]) g_tcu[base + i] = 0ull;
        }

        float s1[U], s2[U];
        #pragma unroll
        for (int i = 0; i < U; i++) {
            s1[i] = tp[i].x * u0 + tp[i].y * u1;
            s2[i] = pe[i].x * v0 + pe[i].y * v1;
            ap0 += tp[i].x; ap1 += tp[i].y;
            ac0 += cnt[i] * pe[i].x; ac1 += cnt[i] * pe[i].y;
        }

        #pragma unroll
        for (int o = 16; o > 0; o >>= 1) {
            #pragma unroll
            for (int i = 0; i < U; i++) {
                s1[i] += __shfl_xor_sync(0xffffffffu, s1[i], o);
                s2[i] += __shfl_xor_sync(0xffffffffu, s2[i], o);
            }
        }

        if (lane == 0) {
            #pragma unroll
            for (int i = 0; i < U; i++) {
                if (val[i]) {
                    int t = base + i;
                    int e = terrain[t] - 1;
                    out[t] = s1[i] + (e == 0 ? tsc0 : tsc1)
                           + cnt[i] * s2[i] + qs[i] + c0;
                    if (e == 0) tcc0 += 1.f; else tcc1 += 1.f;
                }
            }
        }
    }

    atomicAdd(&g_acc[2 * lane],          ap0);
    atomicAdd(&g_acc[2 * lane + 1],      ap1);
    atomicAdd(&g_acc[64 + 2 * lane],     ac0);
    atomicAdd(&g_acc[64 + 2 * lane + 1], ac1);
    if (lane == 0) {
        atomicAdd(&g_acc[144], tcc0);
        atomicAdd(&g_acc[145], tcc1);
    }

    // ---- last-block epilogue (pooled mean -> value MLP) ----
    __threadfence();
    __syncthreads();
    __shared__ bool isLast;
    if (threadIdx.x == 0)
        isLast = (atomicAdd(&g_done, 1u) == gridDim.x - 1);
    __syncthreads();
    if (!isLast) return;

    __shared__ float part[4][64];
    __shared__ float pooled[64];
    __shared__ float h[64];
    int tid = threadIdx.x;
    int c = tid >> 6;       // k-chunk 0..3
    int j = tid & 63;       // output dim
    float fT = (float)T;

    float s = 0.f;
    #pragma unroll 16
    for (int k = c * 16; k < c * 16 + 16; k++) {
        s += g_acc[k]      * tile_fc_w[k * 64 + j];
        s += g_acc[64 + k] * piece_fc_w[(64 + k) * 64 + j];
    }
    #pragma unroll 4
    for (int n = c * 4; n < c * 4 + 4; n++)
        s += g_acc[128 + n] * g_nproj[n * 64 + j];
    if (c == 0) {
        s += g_acc[144] * g_tproj[j] + g_acc[145] * g_tproj[64 + j];
        int an_ = active_nation[0];
        s += fT * tile_fc_b[j] + (float)P * piece_fc_b[j]
           + fT * nation_emb[an_ * 64 + j];
    }
    part[c][j] = s;
    __syncthreads();

    // All g_acc reads are complete: restore zeros for the next replay.
    if (tid < 160) g_acc[tid] = 0.f;
    if (tid == 160) g_done = 0u;

    if (c == 0)
        pooled[j] = (part[0][j] + part[1][j] + part[2][j] + part[3][j]) / fT;
    __syncthreads();

    float hv = 0.f;
    #pragma unroll 16
    for (int k = c * 16; k < c * 16 + 16; k++)
        hv += pooled[k] * value_w1[k * 64 + j];
    part[c][j] = hv;
    __syncthreads();
    if (c == 0) {
        float x = part[0][j] + part[1][j] + part[2][j] + part[3][j] + value_b1[j];
        h[j] = x > 0.f ? x : 0.f;
    }
    __syncthreads();

    if (tid < 32) {
        float v = h[tid] * value_w2[tid] + h[tid + 32] * value_w2[tid + 32];
        #pragma unroll
        for (int o = 16; o > 0; o >>= 1)
            v += __shfl_xor_sync(0xffffffffu, v, o);
        if (tid == 0) {
            out[T]     = end_turn_logit[0];
            out[T + 1] = v + value_b2[0];
        }
    }
}

extern "C" void kernel_launch(void* const* d_in, const int* in_sizes, int n_in,
                              void* d_out, int out_size)
{
    const int*   tile_idxs      = (const int*)  d_in[0];
    const int*   terrain        = (const int*)  d_in[1];
    const int*   nation_idxs    = (const int*)  d_in[2];
    const int*   piece_tidx     = (const int*)  d_in[3];
    const int*   active         = (const int*)  d_in[4];
    const float* tile_pos_emb   = (const float*)d_in[5];
    const float* terrain_emb    = (const float*)d_in[6];
    const float* nation_emb     = (const float*)d_in[7];
    const float* piece_tile_emb = (const float*)d_in[8];
    const float* tile_fc_w      = (const float*)d_in[9];
    const float* tile_fc_b      = (const float*)d_in[10];
    const float* piece_fc_w     = (const float*)d_in[11];
    const float* piece_fc_b     = (const float*)d_in[12];
    const float* tile_policy_w  = (const float*)d_in[13];
    const float* tile_policy_b  = (const float*)d_in[14];
    const float* end_turn       = (const float*)d_in[15];
    const float* value_w1       = (const float*)d_in[16];
    const float* value_b1       = (const float*)d_in[17];
    const float* value_w2       = (const float*)d_in[18];
    const float* value_b2       = (const float*)d_in[19];
    float* out = (float*)d_out;

    int T = in_sizes[0];   // 200000
    int P = in_sizes[2];   // 1000000

    k_pre<<<17, 64>>>(tile_fc_w, tile_fc_b, piece_fc_w, piece_fc_b,
                      tile_policy_w, tile_policy_b, nation_emb, terrain_emb,
                      active);

    k_hist<<<((P >> 2) + 255) / 256, 256>>>(nation_idxs, piece_tidx, P);

    k_tiles<<<592, 256>>>(tile_idxs, terrain, tile_pos_emb, piece_tile_emb, out,
                          T, P,
                          tile_fc_w, tile_fc_b, piece_fc_w, piece_fc_b,
                          nation_emb, active,
                          value_w1, value_b1, value_w2, value_b2, end_turn);
}

// round 11
// speedup vs baseline: 2.1722x; 1.0519x over previous
#include <cuda_runtime.h>

#define NNAT 16
#define MAX_TILES 200000

// Per-tile packed accumulator written by k_hist piece blocks:
//   bits [42:64) = piece count
//   bits [0:42)  = sum over pieces of (q[nation]+pb+4.0) in fixed point, scale 2^30
// INVARIANT: zero outside a kernel_launch invocation (k_tiles restores zeros).
__device__ unsigned long long g_tcu[MAX_TILES];
// [0,64): sum tile_pos; [64,128): sum count_t*pte; [128,144): nation totals; [144,146): terrain counts
__device__ float g_acc[160];
__device__ float g_u[64];          // W_tile_top @ policy_w
__device__ float g_v[64];          // W_piece_bot @ policy_w
__device__ float g_terrsc[2];      // (terrain_emb @ W_tile_bot) @ policy_w
__device__ float g_nproj[16 * 64]; // nation_emb @ W_piece_top
__device__ float g_tproj[2 * 64];  // terrain_emb @ W_tile_bot
__device__ float g_c0;             // (tile_fc_b + nation_emb[active]) . w + policy_b
__device__ unsigned int g_done;    // last-block epilogue counter (reset by epilogue)

#define QSCALE 1073741824.0f   // 2^30
#define QOFF   4.0f
#define CNT_SHIFT 42
#define PARAM_BLOCKS 17

// Fused: blocks 0..15 fold nproj row n; block 16 folds u/v/tproj/terrsc/c0
// (consumed by k_tiles next launch). Blocks >= 17 are piece-histogram blocks;
// they self-compute the packed per-nation increment table (q via the vtop
// factorization), so they don't depend on the param blocks.
__global__ void k_hist(const int* __restrict__ nation_idxs,
                       const int* __restrict__ piece_tile_idxs,
                       int P,
                       const float* __restrict__ tile_fc_w,
                       const float* __restrict__ tile_fc_b,
                       const float* __restrict__ piece_fc_w,
                       const float* __restrict__ piece_fc_b,
                       const float* __restrict__ tile_policy_w,
                       const float* __restrict__ tile_policy_b,
                       const float* __restrict__ nation_emb,
                       const float* __restrict__ terrain_emb,
                       const int*   __restrict__ active_nation)
{
    __shared__ float w[64];
    int tid = threadIdx.x;
    int b = blockIdx.x;

    if (b < PARAM_BLOCKS) {
        __shared__ float rA[64], rB[64], rC[64], rD[64];
        if (tid < 64) w[tid] = tile_policy_w[tid];
        __syncthreads();

        if (b < 16) {
            // nproj[b][j] = sum_k nation_emb[b][k] * piece_fc_w[k][j]
            if (tid < 64) {
                float s = 0.f;
                #pragma unroll 16
                for (int k = 0; k < 64; k++)
                    s += nation_emb[b * 64 + k] * piece_fc_w[k * 64 + tid];
                g_nproj[b * 64 + tid] = s;
            }
        } else {
            if (tid < 64) {
                float su = 0.f, sv = 0.f, t0 = 0.f, t1 = 0.f;
                #pragma unroll 16
                for (int c = 0; c < 64; c++) {
                    su += tile_fc_w[tid * 64 + c] * w[c];          // u[j]
                    sv += piece_fc_w[(64 + tid) * 64 + c] * w[c];  // v[j]
                }
                #pragma unroll 16
                for (int k = 0; k < 64; k++) {
                    float tw = tile_fc_w[(64 + k) * 64 + tid];
                    t0 += terrain_emb[k] * tw;                     // tproj[0][j]
                    t1 += terrain_emb[64 + k] * tw;                // tproj[1][j]
                }
                g_u[tid] = su;
                g_v[tid] = sv;
                g_tproj[tid] = t0;
                g_tproj[64 + tid] = t1;

                int an = active_nation[0];
                rA[tid] = t0 * w[tid];
                rB[tid] = t1 * w[tid];
                rC[tid] = 0.f;  // unused
                rD[tid] = (tile_fc_b[tid] + nation_emb[an * 64 + tid]) * w[tid];
            }
            __syncthreads();
            if (tid < 3) {
                const float* r = (tid == 0) ? rA : (tid == 1) ? rB : rD;
                float s = 0.f;
                #pragma unroll 16
                for (int k = 0; k < 64; k++) s += r[k];
                if (tid == 0) g_terrsc[0] = s;
                else if (tid == 1) g_terrsc[1] = s;
                else g_c0 = s + tile_policy_b[0];
            }
        }
        return;
    }

    // ---- piece-histogram blocks ----
    __shared__ float vtop[64], rP[64];
    __shared__ unsigned long long sq[NNAT];
    __shared__ unsigned int sh[NNAT];

    if (tid < 64) w[tid] = tile_policy_w[tid];
    __syncthreads();

    if (tid < 64) {
        // vtop[k] = piece_fc_w row k (W_piece_top) . w
        const float4* pr = reinterpret_cast<const float4*>(piece_fc_w + tid * 64);
        float s = 0.f;
        #pragma unroll
        for (int c = 0; c < 16; c++) {
            float4 p = pr[c];
            s += p.x * w[4 * c] + p.y * w[4 * c + 1]
               + p.z * w[4 * c + 2] + p.w * w[4 * c + 3];
        }
        vtop[tid] = s;
    } else if (tid < 128) {
        rP[tid - 64] = piece_fc_b[tid - 64] * w[tid - 64];
    }
    __syncthreads();

    if (tid < NNAT) {
        float pb = 0.f;
        #pragma unroll 16
        for (int j = 0; j < 64; j++) pb += rP[j];
        float q = 0.f;
        #pragma unroll 16
        for (int k = 0; k < 64; k++) q += nation_emb[tid * 64 + k] * vtop[k];
        sq[tid] = (unsigned long long)llroundf((q + pb + QOFF) * QSCALE)
                + (1ULL << CNT_SHIFT);
        sh[tid] = 0u;
    }
    __syncthreads();

    int i = (b - PARAM_BLOCKS) * blockDim.x + tid;
    int P4 = P >> 2;
    if (i < P4) {
        int4 n4 = reinterpret_cast<const int4*>(nation_idxs)[i];
        int4 t4 = reinterpret_cast<const int4*>(piece_tile_idxs)[i];
        atomicAdd(&g_tcu[t4.x], sq[n4.x]);
        atomicAdd(&g_tcu[t4.y], sq[n4.y]);
        atomicAdd(&g_tcu[t4.z], sq[n4.z]);
        atomicAdd(&g_tcu[t4.w], sq[n4.w]);
        atomicAdd(&sh[n4.x], 1u); atomicAdd(&sh[n4.y], 1u);
        atomicAdd(&sh[n4.z], 1u); atomicAdd(&sh[n4.w], 1u);
    }
    int rem = P - P4 * 4;
    if (i < rem) {
        int idx = P4 * 4 + i;
        atomicAdd(&g_tcu[piece_tile_idxs[idx]], sq[nation_idxs[idx]]);
        atomicAdd(&sh[nation_idxs[idx]], 1u);
    }
    __syncthreads();
    if (tid < NNAT) atomicAdd(&g_acc[128 + tid], (float)sh[tid]);
}

// Warp-per-tile, U=6 unroll; two 5-level butterflies per tile.
// Self-cleaning: zeroes g_tcu entries after consuming them.
// Last block to finish runs the pooled/value epilogue inline and zeroes g_acc/g_done.
__global__ void k_tiles(const int*   __restrict__ tile_idxs,
                        const int*   __restrict__ terrain,
                        const float* __restrict__ tile_pos_emb,
                        const float* __restrict__ piece_tile_emb,
                        float*       __restrict__ out,
                        int T, int P,
                        const float* __restrict__ tile_fc_w,
                        const float* __restrict__ tile_fc_b,
                        const float* __restrict__ piece_fc_w,
                        const float* __restrict__ piece_fc_b,
                        const float* __restrict__ nation_emb,
                        const int*   __restrict__ active_nation,
                        const float* __restrict__ value_w1,
                        const float* __restrict__ value_b1,
                        const float* __restrict__ value_w2,
                        const float* __restrict__ value_b2,
                        const float* __restrict__ end_turn_logit)
{
    const int U = 6;
    int lane = threadIdx.x & 31;
    int gwid = (blockIdx.x * blockDim.x + threadIdx.x) >> 5;
    int nw   = (gridDim.x * blockDim.x) >> 5;

    float u0 = g_u[2 * lane], u1 = g_u[2 * lane + 1];
    float v0 = g_v[2 * lane], v1 = g_v[2 * lane + 1];
    float c0 = g_c0;
    float tsc0 = g_terrsc[0], tsc1 = g_terrsc[1];

    float ap0 = 0.f, ap1 = 0.f;   // sum tile_pos (this lane's 2 dims)
    float ac0 = 0.f, ac1 = 0.f;   // sum count_t * pte
    float tcc0 = 0.f, tcc1 = 0.f; // terrain counts (lane 0)

    const float2* __restrict__ tp_base = reinterpret_cast<const float2*>(tile_pos_emb);
    const float2* __restrict__ pe_base = reinterpret_cast<const float2*>(piece_tile_emb);

    for (int base = gwid * U; base < T; base += nw * U) {
        float2 tp[U], pe[U];
        unsigned long long pk[U];
        bool   val[U];

        #pragma unroll
        for (int i = 0; i < U; i++) {
            int t = base + i;
            val[i] = (t < T);
            int tt = val[i] ? t : base;
            int row = tile_idxs[tt];
            tp[i] = tp_base[row * 32 + lane];
            pe[i] = pe_base[tt * 32 + lane];
            pk[i] = g_tcu[tt];                // broadcast 8B
        }

        float cnt[U], qs[U];
        #pragma unroll
        for (int i = 0; i < U; i++) {
            if (!val[i]) {
                tp[i] = make_float2(0.f, 0.f);
                pe[i] = make_float2(0.f, 0.f);
                pk[i] = 0ull;
            }
            cnt[i] = (float)(unsigned int)(pk[i] >> CNT_SHIFT);
            qs[i]  = (float)(long long)(pk[i] & ((1ULL << CNT_SHIFT) - 1ull))
                     * (1.0f / QSCALE) - cnt[i] * QOFF;
        }

        // Restore zeros for the next graph replay (values already consumed).
        if (lane == 0) {
            #pragma unroll
            for (int i = 0; i < U; i++)
                if (val[i]) g_tcu[base + i] = 0ull;
        }

        float s1[U], s2[U];
        #pragma unroll
        for (int i = 0; i < U; i++) {
            s1[i] = tp[i].x * u0 + tp[i].y * u1;
            s2[i] = pe[i].x * v0 + pe[i].y * v1;
            ap0 += tp[i].x; ap1 += tp[i].y;
            ac0 += cnt[i] * pe[i].x; ac1 += cnt[i] * pe[i].y;
        }

        #pragma unroll
        for (int o = 16; o > 0; o >>= 1) {
            #pragma unroll
            for (int i = 0; i < U; i++) {
                s1[i] += __shfl_xor_sync(0xffffffffu, s1[i], o);
                s2[i] += __shfl_xor_sync(0xffffffffu, s2[i], o);
            }
        }

        if (lane == 0) {
            #pragma unroll
            for (int i = 0; i < U; i++) {
                if (val[i]) {
                    int t = base + i;
                    int e = terrain[t] - 1;
                    out[t] = s1[i] + (e == 0 ? tsc0 : tsc1)
                           + cnt[i] * s2[i] + qs[i] + c0;
                    if (e == 0) tcc0 += 1.f; else tcc1 += 1.f;
                }
            }
        }
    }

    atomicAdd(&g_acc[2 * lane],          ap0);
    atomicAdd(&g_acc[2 * lane + 1],      ap1);
    atomicAdd(&g_acc[64 + 2 * lane],     ac0);
    atomicAdd(&g_acc[64 + 2 * lane + 1], ac1);
    if (lane == 0) {
        atomicAdd(&g_acc[144], tcc0);
        atomicAdd(&g_acc[145], tcc1);
    }

    // ---- last-block epilogue (pooled mean -> value MLP) ----
    __threadfence();
    __syncthreads();
    __shared__ bool isLast;
    if (threadIdx.x == 0)
        isLast = (atomicAdd(&g_done, 1u) == gridDim.x - 1);
    __syncthreads();
    if (!isLast) return;

    __shared__ float part[4][64];
    __shared__ float pooled[64];
    __shared__ float h[64];
    int tid = threadIdx.x;
    int c = tid >> 6;       // k-chunk 0..3
    int j = tid & 63;       // output dim
    float fT = (float)T;

    float s = 0.f;
    #pragma unroll 16
    for (int k = c * 16; k < c * 16 + 16; k++) {
        s += g_acc[k]      * tile_fc_w[k * 64 + j];
        s += g_acc[64 + k] * piece_fc_w[(64 + k) * 64 + j];
    }
    #pragma unroll 4
    for (int n = c * 4; n < c * 4 + 4; n++)
        s += g_acc[128 + n] * g_nproj[n * 64 + j];
    if (c == 0) {
        s += g_acc[144] * g_tproj[j] + g_acc[145] * g_tproj[64 + j];
        int an_ = active_nation[0];
        s += fT * tile_fc_b[j] + (float)P * piece_fc_b[j]
           + fT * nation_emb[an_ * 64 + j];
    }
    part[c][j] = s;
    __syncthreads();

    // All g_acc reads are complete: restore zeros for the next replay.
    if (tid < 160) g_acc[tid] = 0.f;
    if (tid == 160) g_done = 0u;

    if (c == 0)
        pooled[j] = (part[0][j] + part[1][j] + part[2][j] + part[3][j]) / fT;
    __syncthreads();

    float hv = 0.f;
    #pragma unroll 16
    for (int k = c * 16; k < c * 16 + 16; k++)
        hv += pooled[k] * value_w1[k * 64 + j];
    part[c][j] = hv;
    __syncthreads();
    if (c == 0) {
        float x = part[0][j] + part[1][j] + part[2][j] + part[3][j] + value_b1[j];
        h[j] = x > 0.f ? x : 0.f;
    }
    __syncthreads();

    if (tid < 32) {
        float v = h[tid] * value_w2[tid] + h[tid + 32] * value_w2[tid + 32];
        #pragma unroll
        for (int o = 16; o > 0; o >>= 1)
            v += __shfl_xor_sync(0xffffffffu, v, o);
        if (tid == 0) {
            out[T]     = end_turn_logit[0];
            out[T + 1] = v + value_b2[0];
        }
    }
}

extern "C" void kernel_launch(void* const* d_in, const int* in_sizes, int n_in,
                              void* d_out, int out_size)
{
    const int*   tile_idxs      = (const int*)  d_in[0];
    const int*   terrain        = (const int*)  d_in[1];
    const int*   nation_idxs    = (const int*)  d_in[2];
    const int*   piece_tidx     = (const int*)  d_in[3];
    const int*   active         = (const int*)  d_in[4];
    const float* tile_pos_emb   = (const float*)d_in[5];
    const float* terrain_emb    = (const float*)d_in[6];
    const float* nation_emb     = (const float*)d_in[7];
    const float* piece_tile_emb = (const float*)d_in[8];
    const float* tile_fc_w      = (const float*)d_in[9];
    const float* tile_fc_b      = (const float*)d_in[10];
    const float* piece_fc_w     = (const float*)d_in[11];
    const float* piece_fc_b     = (const float*)d_in[12];
    const float* tile_policy_w  = (const float*)d_in[13];
    const float* tile_policy_b  = (const float*)d_in[14];
    const float* end_turn       = (const float*)d_in[15];
    const float* value_w1       = (const float*)d_in[16];
    const float* value_b1       = (const float*)d_in[17];
    const float* value_w2       = (const float*)d_in[18];
    const float* value_b2       = (const float*)d_in[19];
    float* out = (float*)d_out;

    int T = in_sizes[0];   // 200000
    int P = in_sizes[2];   // 1000000

    int piece_blocks = ((P >> 2) + 255) / 256;
    k_hist<<<PARAM_BLOCKS + piece_blocks, 256>>>(
        nation_idxs, piece_tidx, P,
        tile_fc_w, tile_fc_b, piece_fc_w, piece_fc_b,
        tile_policy_w, tile_policy_b, nation_emb, terrain_emb, active);

    k_tiles<<<592, 256>>>(tile_idxs, terrain, tile_pos_emb, piece_tile_emb, out,
                          T, P,
                          tile_fc_w, tile_fc_b, piece_fc_w, piece_fc_b,
                          nation_emb, active,
                          value_w1, value_b1, value_w2, value_b2, end_turn);
}